// round 8
// baseline (speedup 1.0000x reference)
#include <cuda_runtime.h>
#include <cstdint>

// Problem constants
static constexpr int Bb = 2, Ss = 2048, Hh = 16, DH = 64, Dd = 1024;
static constexpr int KC = 64;                   // K / 16 for both GEMMs

// Scratch (static device globals — no allocations allowed)
__device__ float g_qkv[4096 * 3072];            // x @ w_qkv (normal layout)
__device__ float g_q[Bb * Hh * Ss * DH];        // rope'd, scaled(*log2e), tf32
__device__ float g_k[Bb * Hh * Ss * DH];
__device__ float g_v[Bb * Hh * Ss * DH];
__device__ float g_xp[64 * 4096 * 20];          // packed A for gemm1 (tf32)
__device__ float g_wp[64 * 24 * 16 * 136];      // packed B (w_qkv, tf32)
__device__ float g_wop[64 * 8 * 16 * 136];      // packed B (w_out, tf32)
__device__ float g_aop[64 * 4096 * 20];         // packed A for gemm2 (attn out)

__device__ __forceinline__ uint32_t f2tf(float f) {
    uint32_t u;
    asm("cvt.rna.tf32.f32 %0, %1;" : "=r"(u) : "f"(f));
    return u;
}
__device__ __forceinline__ float f2tff(float f) { return __uint_as_float(f2tf(f)); }

__device__ __forceinline__ float ex2(float x) {
    float y;
    asm("ex2.approx.f32 %0, %1;" : "=f"(y) : "f"(x));
    return y;
}

__device__ __forceinline__ void cp16(void* smem_ptr, const void* gptr) {
    uint32_t sa = (uint32_t)__cvta_generic_to_shared(smem_ptr);
    asm volatile("cp.async.ca.shared.global [%0], [%1], 16;"
                 :: "r"(sa), "l"(gptr));
}

__device__ __forceinline__ void mma8(float (&c)[4], const uint32_t (&a)[4],
                                     uint32_t b0, uint32_t b1) {
    asm volatile(
        "mma.sync.aligned.m16n8k8.row.col.f32.tf32.tf32.f32 "
        "{%0,%1,%2,%3}, {%4,%5,%6,%7}, {%8,%9}, {%0,%1,%2,%3};"
        : "+f"(c[0]), "+f"(c[1]), "+f"(c[2]), "+f"(c[3])
        : "r"(a[0]), "r"(a[1]), "r"(a[2]), "r"(a[3]), "r"(b0), "r"(b1));
}

// ---- mbarrier + 1D bulk-copy helpers ----
__device__ __forceinline__ uint32_t s2u(const void* p) {
    return (uint32_t)__cvta_generic_to_shared(p);
}
__device__ __forceinline__ void mbar_init(uint32_t addr, uint32_t cnt) {
    asm volatile("mbarrier.init.shared.b64 [%0], %1;" :: "r"(addr), "r"(cnt));
}
__device__ __forceinline__ void mbar_expect_tx(uint32_t addr, uint32_t bytes) {
    asm volatile("mbarrier.arrive.expect_tx.shared.b64 _, [%0], %1;"
                 :: "r"(addr), "r"(bytes));
}
__device__ __forceinline__ void mbar_wait(uint32_t addr, uint32_t parity) {
    asm volatile(
        "{\n\t.reg .pred P;\n"
        "W%=:\n\t"
        "mbarrier.try_wait.parity.shared.b64 P, [%0], %1;\n\t"
        "@!P bra W%=;\n\t}"
        :: "r"(addr), "r"(parity) : "memory");
}
__device__ __forceinline__ void bulk_g2s(uint32_t dst, const void* src,
                                         uint32_t bytes, uint32_t mbar) {
    asm volatile(
        "cp.async.bulk.shared::cta.global.mbarrier::complete_tx::bytes "
        "[%0], [%1], %2, [%3];"
        :: "r"(dst), "l"(src), "r"(bytes), "r"(mbar) : "memory");
}

// ---------------------------------------------------------------------------
// Pack kernels (R6 proven): contiguous, padded, tf32-rounded tiles in gmem.
// A pack: X[M][1024] -> Xp[kc][M][20]  (cols 0-15 data, 16-19 pad)
// ---------------------------------------------------------------------------
__global__ __launch_bounds__(256) void pack_a(
    const float* __restrict__ X, float* __restrict__ Xp) {
    int idx = blockIdx.x * 256 + threadIdx.x;   // over 4096*1024
    int m = idx >> 10, k = idx & 1023;
    Xp[((size_t)(k >> 4) * 4096 + m) * 20 + (k & 15)] = f2tff(X[idx]);
}

// B pack: W[1024][N] -> Wp[kc][nb][kr(16)][136]  (cols 0-127 data, pad 8)
__global__ __launch_bounds__(256) void pack_b(
    const float* __restrict__ W, float* __restrict__ Wp, int N) {
    int idx = blockIdx.x * 256 + threadIdx.x;   // over 1024*N
    int k = idx / N, n = idx - k * N;
    size_t chunk = (size_t)(k >> 4) * (N >> 7) + (n >> 7);
    Wp[chunk * 2176 + (k & 15) * 136 + (n & 127)] = f2tff(W[idx]);
}

// ---------------------------------------------------------------------------
// tf32 GEMM (R6 proven, at mma.sync roofline): packed operands, bulk pipeline.
// Block 128x128, BK=16, 256 threads, 3-stage mbarrier pipeline.
// ---------------------------------------------------------------------------
static constexpr int AST_W = 128 * 20;          // 2560 words
static constexpr int BST_W = 16 * 136;          // 2176 words
static constexpr int STG_W = AST_W + BST_W;     // 4736 words = 18944 B
static constexpr int GEMM_SMEM = 3 * STG_W * 4; // 56832 B

__global__ __launch_bounds__(256) void gemm_packed(
    const float* __restrict__ Ap, const float* __restrict__ Bp,
    float* __restrict__ C, int N) {
    extern __shared__ uint32_t gsm[];
    __shared__ uint64_t gmb[3];

    const int NB = N >> 7;
    const int tid = threadIdx.x, lane = tid & 31, warp = tid >> 5;
    const int wm = (warp >> 2) * 64, wn = (warp & 3) * 32;
    const int lr = lane >> 2, lq = lane & 3;
    const int bm = blockIdx.y * 128, nb = blockIdx.x;

    const uint32_t mb0 = s2u(gmb);
    const uint32_t smem_base = s2u(gsm);

    if (tid == 0) {
        mbar_init(mb0, 1);
        mbar_init(mb0 + 8, 1);
        mbar_init(mb0 + 16, 1);
        asm volatile("fence.proxy.async.shared::cta;" ::: "memory");
    }
    __syncthreads();

    auto issue = [&](int i) {
        if (tid == 0) {
            int st = i % 3;
            uint32_t m = mb0 + st * 8;
            uint32_t dst = smem_base + st * (STG_W * 4);
            mbar_expect_tx(m, STG_W * 4);
            bulk_g2s(dst, Ap + ((size_t)i * 4096 + bm) * 20, AST_W * 4, m);
            bulk_g2s(dst + AST_W * 4, Bp + (size_t)(i * NB + nb) * BST_W,
                     BST_W * 4, m);
        }
    };

    float acc[4][4][4];
#pragma unroll
    for (int mt = 0; mt < 4; mt++)
#pragma unroll
        for (int nt = 0; nt < 4; nt++)
#pragma unroll
            for (int i = 0; i < 4; i++) acc[mt][nt][i] = 0.f;

    issue(0);
    issue(1);
    issue(2);

    for (int i = 0; i < KC; i++) {
        const int st = i % 3;
        mbar_wait(mb0 + st * 8, (i / 3) & 1);
        const uint32_t* As = gsm + st * STG_W;        // [128][20]
        const uint32_t* Bs = As + AST_W;              // [16][136]

#pragma unroll
        for (int ks = 0; ks < 16; ks += 8) {
            uint32_t a[4][4], b[4][2];
#pragma unroll
            for (int mt = 0; mt < 4; mt++) {
                int r0 = (wm + mt * 16 + lr) * 20, c0 = ks + lq;
                a[mt][0] = As[r0 + c0];
                a[mt][1] = As[r0 + 160 + c0];         // +8 rows
                a[mt][2] = As[r0 + c0 + 4];
                a[mt][3] = As[r0 + 160 + c0 + 4];
            }
#pragma unroll
            for (int nt = 0; nt < 4; nt++) {
                int cc = wn + nt * 8 + lr, kr = ks + lq;
                b[nt][0] = Bs[kr * 136 + cc];
                b[nt][1] = Bs[(kr + 4) * 136 + cc];
            }
#pragma unroll
            for (int mt = 0; mt < 4; mt++)
#pragma unroll
                for (int nt = 0; nt < 4; nt++)
                    mma8(acc[mt][nt], a[mt], b[nt][0], b[nt][1]);
        }
        __syncthreads();
        if (i + 3 < KC) issue(i + 3);
    }

#pragma unroll
    for (int mt = 0; mt < 4; mt++)
#pragma unroll
        for (int nt = 0; nt < 4; nt++) {
            int row = bm + wm + mt * 16 + lr;
            int col = (nb << 7) + wn + nt * 8 + (lq << 1);
            *(float2*)&C[(size_t)row * N + col] =
                make_float2(acc[mt][nt][0], acc[mt][nt][1]);
            *(float2*)&C[(size_t)(row + 8) * N + col] =
                make_float2(acc[mt][nt][2], acc[mt][nt][3]);
        }
}

// ---------------------------------------------------------------------------
// RoPE (proven): one thread per (b, s, d<32), looping over heads.
// ---------------------------------------------------------------------------
__global__ __launch_bounds__(256) void rope_kernel(
    const float* __restrict__ qkv, const float* __restrict__ freqs,
    float* __restrict__ Qo, float* __restrict__ Ko, float* __restrict__ Vo) {
    int idx = blockIdx.x * 256 + threadIdx.x;
    int d = idx & 31;
    int bs = idx >> 5;
    int s = bs & 2047;

    float f1 = freqs[s * 64 + d], f2 = freqs[s * 64 + d + 32];
    float c1, s1, c2, s2;
    sincosf(f1, &s1, &c1);
    sincosf(f2, &s2, &c2);

    const float scale = 0.125f * 1.4426950408889634f;
    const float* base0 = qkv + (size_t)bs * 3072 + d;
    int b = bs >> 11;

#pragma unroll 4
    for (int h = 0; h < Hh; h++) {
        const float* base = base0 + h * 64;
        float q1 = base[0], q2 = base[32];
        float k1 = base[1024], k2 = base[1024 + 32];
        float v1 = base[2048], v2 = base[2048 + 32];

        float qo1 = (q1 * c1 - q2 * s1) * scale;
        float qo2 = (q2 * c2 + q1 * s2) * scale;
        float ko1 = k1 * c1 - k2 * s1;
        float ko2 = k2 * c2 + k1 * s2;

        size_t ob = ((size_t)(b * Hh + h) * Ss + s) * 64 + d;
        Qo[ob]      = f2tff(qo1);
        Qo[ob + 32] = f2tff(qo2);
        Ko[ob]      = f2tff(ko1);
        Ko[ob + 32] = f2tff(ko2);
        Vo[ob]      = f2tff(v1);
        Vo[ob + 32] = f2tff(v2);
    }
}

// ---------------------------------------------------------------------------
// Causal flash attention v4. Br=128 (8 warps x 16 rows), Bc=64.
// K [kv][d] pad-68, V row-permuted pad-72. 3-stage cp.async pipeline with a
// SINGLE __syncthreads per tile (3 buffers make re-issue safe after one sync).
// Fully-masked warps skip compute on the diagonal upper tile.
// Epilogue writes the PACKED A layout for gemm2: aop[kc][row][20], tf32.
// ---------------------------------------------------------------------------
static constexpr int KS_WORDS = 64 * 68;
static constexpr int VS_WORDS = 64 * 72;
static constexpr int STAGE_W = KS_WORDS + VS_WORDS;            // 8704 words
static constexpr int ATTN_SMEM_BYTES = 3 * STAGE_W * 4;        // 104448 B

__global__ __launch_bounds__(256, 2) void attn_kernel(
    const float* __restrict__ Q, const float* __restrict__ K,
    const float* __restrict__ V, float* __restrict__ AOP) {
    extern __shared__ uint32_t dynsmem[];
    // stage s: K at dynsmem + s*STAGE_W (64x68), V at +KS_WORDS (64x72)

    const int qt = gridDim.x - 1 - blockIdx.x;
    const int h = blockIdx.y, b = blockIdx.z;
    const int tid = threadIdx.x, lane = tid & 31, warp = tid >> 5;
    const int lr = lane >> 2, lq = lane & 3;
    const int q0 = qt * 128;

    const size_t bh = (size_t)(b * Hh + h) * Ss;
    const float* Qg = Q + (bh + q0) * 64;
    const float* Kg = K + bh * 64;
    const float* Vg = V + bh * 64;

    uint32_t qf[8][4];
    {
        int r0 = warp * 16 + lr;
#pragma unroll
        for (int k8 = 0; k8 < 8; k8++) {
            int c = k8 * 8 + lq;
            qf[k8][0] = __float_as_uint(Qg[r0 * 64 + c]);
            qf[k8][1] = __float_as_uint(Qg[(r0 + 8) * 64 + c]);
            qf[k8][2] = __float_as_uint(Qg[r0 * 64 + c + 4]);
            qf[k8][3] = __float_as_uint(Qg[(r0 + 8) * 64 + c + 4]);
        }
    }

    float o[8][4];
#pragma unroll
    for (int dn = 0; dn < 8; dn++)
#pragma unroll
        for (int i = 0; i < 4; i++) o[dn][i] = 0.f;
    float m0 = -1e30f, m1 = -1e30f, l0 = 0.f, l1 = 0.f;

    const int lrow = tid >> 4;
    const int lcol = (tid & 15) << 2;

    auto issue_tile = [&](int jt, int st) {
        uint32_t* Ksb = dynsmem + st * STAGE_W;
        uint32_t* Vsb = Ksb + KS_WORDS;
        const float* kb = Kg + (size_t)(jt * 64) * 64;
        const float* vb = Vg + (size_t)(jt * 64) * 64;
#pragma unroll
        for (int u = 0; u < 4; u++) {
            int r = lrow + 16 * u;
            cp16(&Ksb[r * 68 + lcol], kb + r * 64 + lcol);
            int g = r & 7;
            int slot = (r & ~7) | ((g & 1) ? ((g >> 1) + 4) : (g >> 1));
            cp16(&Vsb[slot * 72 + lcol], vb + r * 64 + lcol);
        }
        asm volatile("cp.async.commit_group;");
    };

    const int jmax = 2 * qt + 1;
    issue_tile(0, 0);
    issue_tile(1, 1);          // jmax >= 1 always

    const int r1 = q0 + warp * 16 + lr;
    const int warp_rmax = q0 + warp * 16 + 15;

    for (int jt = 0; jt <= jmax; jt++) {
        const int cur = jt % 3;
        if (jt < jmax)
            asm volatile("cp.async.wait_group 1;");
        else
            asm volatile("cp.async.wait_group 0;");
        __syncthreads();       // copies visible + all warps done with buf (jt-1)%3
        if (jt + 2 <= jmax) issue_tile(jt + 2, (jt + 2) % 3);

        // Fully-masked warp on the diagonal upper tile: skip all compute.
        if (jt * 64 > warp_rmax) continue;

        const uint32_t* Ksb = dynsmem + cur * STAGE_W;
        const uint32_t* Vsb = Ksb + KS_WORDS;

        float sc[8][4];
#pragma unroll
        for (int nt = 0; nt < 8; nt++)
#pragma unroll
            for (int i = 0; i < 4; i++) sc[nt][i] = 0.f;
#pragma unroll
        for (int k8 = 0; k8 < 8; k8++)
#pragma unroll
            for (int nt = 0; nt < 8; nt++)
                mma8(sc[nt], qf[k8],
                     Ksb[(nt * 8 + lr) * 68 + k8 * 8 + lq],
                     Ksb[(nt * 8 + lr) * 68 + k8 * 8 + lq + 4]);

        if (jt >= 2 * qt) {
#pragma unroll
            for (int nt = 0; nt < 8; nt++) {
                int key = jt * 64 + nt * 8 + (lq << 1);
                if (key > r1) sc[nt][0] = -1e30f;
                if (key + 1 > r1) sc[nt][1] = -1e30f;
                if (key > r1 + 8) sc[nt][2] = -1e30f;
                if (key + 1 > r1 + 8) sc[nt][3] = -1e30f;
            }
        }

        float mx0 = -1e30f, mx1 = -1e30f;
#pragma unroll
        for (int nt = 0; nt < 8; nt++) {
            mx0 = fmaxf(mx0, fmaxf(sc[nt][0], sc[nt][1]));
            mx1 = fmaxf(mx1, fmaxf(sc[nt][2], sc[nt][3]));
        }
        mx0 = fmaxf(mx0, __shfl_xor_sync(0xffffffffu, mx0, 1));
        mx0 = fmaxf(mx0, __shfl_xor_sync(0xffffffffu, mx0, 2));
        mx1 = fmaxf(mx1, __shfl_xor_sync(0xffffffffu, mx1, 1));
        mx1 = fmaxf(mx1, __shfl_xor_sync(0xffffffffu, mx1, 2));
        float mn0 = fmaxf(m0, mx0), mn1 = fmaxf(m1, mx1);
        float fac0 = ex2(m0 - mn0), fac1 = ex2(m1 - mn1);

        float s0 = 0.f, s1 = 0.f;
#pragma unroll
        for (int nt = 0; nt < 8; nt++) {
            float p0 = ex2(sc[nt][0] - mn0);
            float p1 = ex2(sc[nt][1] - mn0);
            float p2 = ex2(sc[nt][2] - mn1);
            float p3 = ex2(sc[nt][3] - mn1);
            s0 += p0 + p1;
            s1 += p2 + p3;
            sc[nt][0] = f2tff(p0);
            sc[nt][1] = f2tff(p1);
            sc[nt][2] = f2tff(p2);
            sc[nt][3] = f2tff(p3);
        }
        s0 += __shfl_xor_sync(0xffffffffu, s0, 1);
        s0 += __shfl_xor_sync(0xffffffffu, s0, 2);
        s1 += __shfl_xor_sync(0xffffffffu, s1, 1);
        s1 += __shfl_xor_sync(0xffffffffu, s1, 2);
        l0 = l0 * fac0 + s0;
        l1 = l1 * fac1 + s1;
        m0 = mn0;
        m1 = mn1;
#pragma unroll
        for (int dn = 0; dn < 8; dn++) {
            o[dn][0] *= fac0; o[dn][1] *= fac0;
            o[dn][2] *= fac1; o[dn][3] *= fac1;
        }

#pragma unroll
        for (int k8 = 0; k8 < 8; k8++) {
            uint32_t af[4] = {__float_as_uint(sc[k8][0]), __float_as_uint(sc[k8][2]),
                              __float_as_uint(sc[k8][1]), __float_as_uint(sc[k8][3])};
#pragma unroll
            for (int dn = 0; dn < 8; dn++)
                mma8(o[dn], af,
                     Vsb[(k8 * 8 + lq) * 72 + dn * 8 + lr],
                     Vsb[(k8 * 8 + lq + 4) * 72 + dn * 8 + lr]);
        }
    }

    // ---- epilogue: normalize + tf32-round, write PACKED aop[kc][row][20] ----
    float i0 = 1.0f / l0, i1 = 1.0f / l1;
    int grow = b * Ss + q0 + warp * 16 + lr;
#pragma unroll
    for (int dn = 0; dn < 8; dn++) {
        int e = dn * 8 + (lq << 1);           // 0..62, even
        int kc = h * 4 + (e >> 4);
        int ki = e & 15;
        float* p0 = AOP + ((size_t)kc * 4096 + grow) * 20 + ki;
        float* p1 = AOP + ((size_t)kc * 4096 + grow + 8) * 20 + ki;
        *(float2*)p0 = make_float2(f2tff(o[dn][0] * i0), f2tff(o[dn][1] * i0));
        *(float2*)p1 = make_float2(f2tff(o[dn][2] * i1), f2tff(o[dn][3] * i1));
    }
}

// ---------------------------------------------------------------------------
extern "C" void kernel_launch(void* const* d_in, const int* in_sizes, int n_in,
                              void* d_out, int out_size) {
    const float* x = (const float*)d_in[0];
    const float* w_qkv = (const float*)d_in[1];
    const float* w_out = (const float*)d_in[2];
    const float* freqs = (const float*)d_in[3];
    float* out = (float*)d_out;

    float *qkv, *q, *k, *v, *xp, *wp, *wop, *aop;
    cudaGetSymbolAddress((void**)&qkv, g_qkv);
    cudaGetSymbolAddress((void**)&q, g_q);
    cudaGetSymbolAddress((void**)&k, g_k);
    cudaGetSymbolAddress((void**)&v, g_v);
    cudaGetSymbolAddress((void**)&xp, g_xp);
    cudaGetSymbolAddress((void**)&wp, g_wp);
    cudaGetSymbolAddress((void**)&wop, g_wop);
    cudaGetSymbolAddress((void**)&aop, g_aop);

    cudaFuncSetAttribute(attn_kernel,
                         cudaFuncAttributeMaxDynamicSharedMemorySize,
                         ATTN_SMEM_BYTES);
    cudaFuncSetAttribute(gemm_packed,
                         cudaFuncAttributeMaxDynamicSharedMemorySize,
                         GEMM_SMEM);

    // 0) Pack operands (tf32, padded conflict-free layouts, contiguous tiles)
    pack_a<<<(4096 * 1024) / 256, 256>>>(x, xp);
    pack_b<<<(1024 * 3072) / 256, 256>>>(w_qkv, wp, 3072);
    pack_b<<<(1024 * 1024) / 256, 256>>>(w_out, wop, 1024);

    // 1) QKV projection: [4096,1024] @ [1024,3072]
    gemm_packed<<<dim3(24, 32), 256, GEMM_SMEM>>>(xp, wp, qkv, 3072);
    // 2) RoPE + head transpose + tf32 round
    rope_kernel<<<(Bb * Ss * 32) / 256, 256>>>(qkv, freqs, q, k, v);
    // 3) Causal flash attention (writes packed aop)
    attn_kernel<<<dim3(Ss / 128, Hh, Bb), 256, ATTN_SMEM_BYTES>>>(q, k, v, aop);
    // 4) Output projection: [4096,1024] @ [1024,1024]
    gemm_packed<<<dim3(8, 32), 256, GEMM_SMEM>>>(aop, wop, out, 1024);
}

// round 9
// speedup vs baseline: 1.0644x; 1.0644x over previous
#include <cuda_runtime.h>
#include <cstdint>

// Problem constants
static constexpr int Bb = 2, Ss = 2048, Hh = 16, DH = 64, Dd = 1024;
static constexpr int KC = 64;                   // K / 16 for both GEMMs

// Scratch (static device globals — no allocations allowed)
__device__ float g_qkv[4096 * 3072];            // x @ w_qkv (normal layout)
__device__ float g_q[Bb * Hh * Ss * DH];        // rope'd, scaled(*log2e), tf32
__device__ float g_k[Bb * Hh * Ss * DH];
__device__ float g_v[Bb * Hh * Ss * DH];
__device__ float g_xp[64 * 4096 * 20];          // packed A for gemm1 (tf32)
__device__ float g_wp[64 * 24 * 16 * 136];      // packed B (w_qkv, tf32)
__device__ float g_wop[64 * 8 * 16 * 136];      // packed B (w_out, tf32)
__device__ float g_aop[64 * 4096 * 20];         // packed A for gemm2 (attn out)

__device__ __forceinline__ uint32_t f2tf(float f) {
    uint32_t u;
    asm("cvt.rna.tf32.f32 %0, %1;" : "=r"(u) : "f"(f));
    return u;
}
__device__ __forceinline__ float f2tff(float f) { return __uint_as_float(f2tf(f)); }

__device__ __forceinline__ float ex2(float x) {
    float y;
    asm("ex2.approx.f32 %0, %1;" : "=f"(y) : "f"(x));
    return y;
}

__device__ __forceinline__ void cp16(void* smem_ptr, const void* gptr) {
    uint32_t sa = (uint32_t)__cvta_generic_to_shared(smem_ptr);
    asm volatile("cp.async.ca.shared.global [%0], [%1], 16;"
                 :: "r"(sa), "l"(gptr));
}

__device__ __forceinline__ void mma8(float (&c)[4], const uint32_t (&a)[4],
                                     uint32_t b0, uint32_t b1) {
    asm volatile(
        "mma.sync.aligned.m16n8k8.row.col.f32.tf32.tf32.f32 "
        "{%0,%1,%2,%3}, {%4,%5,%6,%7}, {%8,%9}, {%0,%1,%2,%3};"
        : "+f"(c[0]), "+f"(c[1]), "+f"(c[2]), "+f"(c[3])
        : "r"(a[0]), "r"(a[1]), "r"(a[2]), "r"(a[3]), "r"(b0), "r"(b1));
}

// ---- mbarrier + 1D bulk-copy helpers ----
__device__ __forceinline__ uint32_t s2u(const void* p) {
    return (uint32_t)__cvta_generic_to_shared(p);
}
__device__ __forceinline__ void mbar_init(uint32_t addr, uint32_t cnt) {
    asm volatile("mbarrier.init.shared.b64 [%0], %1;" :: "r"(addr), "r"(cnt));
}
__device__ __forceinline__ void mbar_expect_tx(uint32_t addr, uint32_t bytes) {
    asm volatile("mbarrier.arrive.expect_tx.shared.b64 _, [%0], %1;"
                 :: "r"(addr), "r"(bytes));
}
__device__ __forceinline__ void mbar_wait(uint32_t addr, uint32_t parity) {
    asm volatile(
        "{\n\t.reg .pred P;\n"
        "W%=:\n\t"
        "mbarrier.try_wait.parity.shared.b64 P, [%0], %1;\n\t"
        "@!P bra W%=;\n\t}"
        :: "r"(addr), "r"(parity) : "memory");
}
__device__ __forceinline__ void bulk_g2s(uint32_t dst, const void* src,
                                         uint32_t bytes, uint32_t mbar) {
    asm volatile(
        "cp.async.bulk.shared::cta.global.mbarrier::complete_tx::bytes "
        "[%0], [%1], %2, [%3];"
        :: "r"(dst), "l"(src), "r"(bytes), "r"(mbar) : "memory");
}

// ---------------------------------------------------------------------------
// Pack kernels (R6 proven): contiguous, padded, tf32-rounded tiles in gmem.
// A pack: X[M][1024] -> Xp[kc][M][20]  (cols 0-15 data, 16-19 pad)
// ---------------------------------------------------------------------------
__global__ __launch_bounds__(256) void pack_a(
    const float* __restrict__ X, float* __restrict__ Xp) {
    int idx = blockIdx.x * 256 + threadIdx.x;   // over 4096*1024
    int m = idx >> 10, k = idx & 1023;
    Xp[((size_t)(k >> 4) * 4096 + m) * 20 + (k & 15)] = f2tff(X[idx]);
}

// B pack: W[1024][N] -> Wp[kc][nb][kr(16)][136]  (cols 0-127 data, pad 8)
__global__ __launch_bounds__(256) void pack_b(
    const float* __restrict__ W, float* __restrict__ Wp, int N) {
    int idx = blockIdx.x * 256 + threadIdx.x;   // over 1024*N
    int k = idx / N, n = idx - k * N;
    size_t chunk = (size_t)(k >> 4) * (N >> 7) + (n >> 7);
    Wp[chunk * 2176 + (k & 15) * 136 + (n & 127)] = f2tff(W[idx]);
}

// ---------------------------------------------------------------------------
// tf32 GEMM v4: 256x128 output tile per CTA (double work per barrier).
// 256 threads, 8 warps as 4x2 grid of 64x64 warp tiles (mt 4 x nt 8 subtiles).
// BK=16, 3-stage mbarrier + bulk-copy pipeline (A 20480B + B 8704B per stage).
// ---------------------------------------------------------------------------
static constexpr int AST_W = 256 * 20;          // 5120 words
static constexpr int BST_W = 16 * 136;          // 2176 words
static constexpr int STG_W = AST_W + BST_W;     // 7296 words = 29184 B
static constexpr int GEMM_SMEM = 3 * STG_W * 4; // 87552 B

__global__ __launch_bounds__(256) void gemm_packed(
    const float* __restrict__ Ap, const float* __restrict__ Bp,
    float* __restrict__ C, int N) {
    extern __shared__ uint32_t gsm[];
    __shared__ uint64_t gmb[3];

    const int NB = N >> 7;
    const int tid = threadIdx.x, lane = tid & 31, warp = tid >> 5;
    const int wm = (warp >> 1) * 64, wn = (warp & 1) * 64;
    const int lr = lane >> 2, lq = lane & 3;
    const int bm = blockIdx.y * 256, nb = blockIdx.x;

    const uint32_t mb0 = s2u(gmb);
    const uint32_t smem_base = s2u(gsm);

    if (tid == 0) {
        mbar_init(mb0, 1);
        mbar_init(mb0 + 8, 1);
        mbar_init(mb0 + 16, 1);
        asm volatile("fence.proxy.async.shared::cta;" ::: "memory");
    }
    __syncthreads();

    auto issue = [&](int i) {
        if (tid == 0) {
            int st = i % 3;
            uint32_t m = mb0 + st * 8;
            uint32_t dst = smem_base + st * (STG_W * 4);
            mbar_expect_tx(m, STG_W * 4);
            bulk_g2s(dst, Ap + ((size_t)i * 4096 + bm) * 20, AST_W * 4, m);
            bulk_g2s(dst + AST_W * 4, Bp + (size_t)(i * NB + nb) * BST_W,
                     BST_W * 4, m);
        }
    };

    float acc[4][8][4];
#pragma unroll
    for (int mt = 0; mt < 4; mt++)
#pragma unroll
        for (int nt = 0; nt < 8; nt++)
#pragma unroll
            for (int i = 0; i < 4; i++) acc[mt][nt][i] = 0.f;

    issue(0);
    issue(1);
    issue(2);

    for (int i = 0; i < KC; i++) {
        const int st = i % 3;
        mbar_wait(mb0 + st * 8, (i / 3) & 1);
        const uint32_t* As = gsm + st * STG_W;        // [256][20]
        const uint32_t* Bs = As + AST_W;              // [16][136]

#pragma unroll
        for (int ks = 0; ks < 16; ks += 8) {
            uint32_t a[4][4], b[8][2];
#pragma unroll
            for (int mt = 0; mt < 4; mt++) {
                int r0 = (wm + mt * 16 + lr) * 20, c0 = ks + lq;
                a[mt][0] = As[r0 + c0];
                a[mt][1] = As[r0 + 160 + c0];         // +8 rows
                a[mt][2] = As[r0 + c0 + 4];
                a[mt][3] = As[r0 + 160 + c0 + 4];
            }
#pragma unroll
            for (int nt = 0; nt < 8; nt++) {
                int cc = wn + nt * 8 + lr, kr = ks + lq;
                b[nt][0] = Bs[kr * 136 + cc];
                b[nt][1] = Bs[(kr + 4) * 136 + cc];
            }
#pragma unroll
            for (int mt = 0; mt < 4; mt++)
#pragma unroll
                for (int nt = 0; nt < 8; nt++)
                    mma8(acc[mt][nt], a[mt], b[nt][0], b[nt][1]);
        }
        __syncthreads();
        if (i + 3 < KC) issue(i + 3);
    }

#pragma unroll
    for (int mt = 0; mt < 4; mt++)
#pragma unroll
        for (int nt = 0; nt < 8; nt++) {
            int row = bm + wm + mt * 16 + lr;
            int col = (nb << 7) + wn + nt * 8 + (lq << 1);
            *(float2*)&C[(size_t)row * N + col] =
                make_float2(acc[mt][nt][0], acc[mt][nt][1]);
            *(float2*)&C[(size_t)(row + 8) * N + col] =
                make_float2(acc[mt][nt][2], acc[mt][nt][3]);
        }
}

// ---------------------------------------------------------------------------
// RoPE (proven): one thread per (b, s, d<32), looping over heads.
// ---------------------------------------------------------------------------
__global__ __launch_bounds__(256) void rope_kernel(
    const float* __restrict__ qkv, const float* __restrict__ freqs,
    float* __restrict__ Qo, float* __restrict__ Ko, float* __restrict__ Vo) {
    int idx = blockIdx.x * 256 + threadIdx.x;
    int d = idx & 31;
    int bs = idx >> 5;
    int s = bs & 2047;

    float f1 = freqs[s * 64 + d], f2 = freqs[s * 64 + d + 32];
    float c1, s1, c2, s2;
    sincosf(f1, &s1, &c1);
    sincosf(f2, &s2, &c2);

    const float scale = 0.125f * 1.4426950408889634f;
    const float* base0 = qkv + (size_t)bs * 3072 + d;
    int b = bs >> 11;

#pragma unroll 4
    for (int h = 0; h < Hh; h++) {
        const float* base = base0 + h * 64;
        float q1 = base[0], q2 = base[32];
        float k1 = base[1024], k2 = base[1024 + 32];
        float v1 = base[2048], v2 = base[2048 + 32];

        float qo1 = (q1 * c1 - q2 * s1) * scale;
        float qo2 = (q2 * c2 + q1 * s2) * scale;
        float ko1 = k1 * c1 - k2 * s1;
        float ko2 = k2 * c2 + k1 * s2;

        size_t ob = ((size_t)(b * Hh + h) * Ss + s) * 64 + d;
        Qo[ob]      = f2tff(qo1);
        Qo[ob + 32] = f2tff(qo2);
        Ko[ob]      = f2tff(ko1);
        Ko[ob + 32] = f2tff(ko2);
        Vo[ob]      = f2tff(v1);
        Vo[ob + 32] = f2tff(v2);
    }
}

// ---------------------------------------------------------------------------
// Causal flash attention (EXACT R6 version — best measured). Br=128, Bc=64.
// K [kv][d] pad-68, V row-permuted pad-72, cp.async double-buffered.
// Epilogue writes the PACKED A layout for gemm2: aop[kc][row][20], tf32.
// ---------------------------------------------------------------------------
static constexpr int KS_WORDS = 64 * 68;
static constexpr int VS_WORDS = 64 * 72;
static constexpr int ATTN_SMEM_BYTES = (2 * KS_WORDS + 2 * VS_WORDS) * 4;  // 71680

__global__ __launch_bounds__(256) void attn_kernel(
    const float* __restrict__ Q, const float* __restrict__ K,
    const float* __restrict__ V, float* __restrict__ AOP) {
    extern __shared__ uint32_t dynsmem[];
    uint32_t (*Ks)[64][68] = reinterpret_cast<uint32_t (*)[64][68]>(dynsmem);
    uint32_t (*Vs)[64][72] =
        reinterpret_cast<uint32_t (*)[64][72]>(dynsmem + 2 * KS_WORDS);

    const int qt = gridDim.x - 1 - blockIdx.x;
    const int h = blockIdx.y, b = blockIdx.z;
    const int tid = threadIdx.x, lane = tid & 31, warp = tid >> 5;
    const int lr = lane >> 2, lq = lane & 3;
    const int q0 = qt * 128;

    const size_t bh = (size_t)(b * Hh + h) * Ss;
    const float* Qg = Q + (bh + q0) * 64;
    const float* Kg = K + bh * 64;
    const float* Vg = V + bh * 64;

    uint32_t qf[8][4];
    {
        int r0 = warp * 16 + lr;
#pragma unroll
        for (int k8 = 0; k8 < 8; k8++) {
            int c = k8 * 8 + lq;
            qf[k8][0] = __float_as_uint(Qg[r0 * 64 + c]);
            qf[k8][1] = __float_as_uint(Qg[(r0 + 8) * 64 + c]);
            qf[k8][2] = __float_as_uint(Qg[r0 * 64 + c + 4]);
            qf[k8][3] = __float_as_uint(Qg[(r0 + 8) * 64 + c + 4]);
        }
    }

    float o[8][4];
#pragma unroll
    for (int dn = 0; dn < 8; dn++)
#pragma unroll
        for (int i = 0; i < 4; i++) o[dn][i] = 0.f;
    float m0 = -1e30f, m1 = -1e30f, l0 = 0.f, l1 = 0.f;

    const int lrow = tid >> 4;
    const int lcol = (tid & 15) << 2;

    auto issue_tile = [&](int jt, int buf) {
        const float* kb = Kg + (size_t)(jt * 64) * 64;
        const float* vb = Vg + (size_t)(jt * 64) * 64;
#pragma unroll
        for (int u = 0; u < 4; u++) {
            int r = lrow + 16 * u;
            cp16(&Ks[buf][r][lcol], kb + r * 64 + lcol);
            int g = r & 7;
            int slot = (r & ~7) | ((g & 1) ? ((g >> 1) + 4) : (g >> 1));
            cp16(&Vs[buf][slot][lcol], vb + r * 64 + lcol);
        }
        asm volatile("cp.async.commit_group;");
    };

    const int jmax = 2 * qt + 1;
    issue_tile(0, 0);

    for (int jt = 0; jt <= jmax; jt++) {
        const int cur = jt & 1;
        if (jt < jmax) {
            issue_tile(jt + 1, cur ^ 1);
            asm volatile("cp.async.wait_group 1;");
        } else {
            asm volatile("cp.async.wait_group 0;");
        }
        __syncthreads();

        float sc[8][4];
#pragma unroll
        for (int nt = 0; nt < 8; nt++)
#pragma unroll
            for (int i = 0; i < 4; i++) sc[nt][i] = 0.f;
#pragma unroll
        for (int k8 = 0; k8 < 8; k8++)
#pragma unroll
            for (int nt = 0; nt < 8; nt++)
                mma8(sc[nt], qf[k8],
                     Ks[cur][nt * 8 + lr][k8 * 8 + lq],
                     Ks[cur][nt * 8 + lr][k8 * 8 + lq + 4]);

        if (jt >= 2 * qt) {
            int r1 = q0 + warp * 16 + lr;
#pragma unroll
            for (int nt = 0; nt < 8; nt++) {
                int key = jt * 64 + nt * 8 + (lq << 1);
                if (key > r1) sc[nt][0] = -1e30f;
                if (key + 1 > r1) sc[nt][1] = -1e30f;
                if (key > r1 + 8) sc[nt][2] = -1e30f;
                if (key + 1 > r1 + 8) sc[nt][3] = -1e30f;
            }
        }

        float mx0 = -1e30f, mx1 = -1e30f;
#pragma unroll
        for (int nt = 0; nt < 8; nt++) {
            mx0 = fmaxf(mx0, fmaxf(sc[nt][0], sc[nt][1]));
            mx1 = fmaxf(mx1, fmaxf(sc[nt][2], sc[nt][3]));
        }
        mx0 = fmaxf(mx0, __shfl_xor_sync(0xffffffffu, mx0, 1));
        mx0 = fmaxf(mx0, __shfl_xor_sync(0xffffffffu, mx0, 2));
        mx1 = fmaxf(mx1, __shfl_xor_sync(0xffffffffu, mx1, 1));
        mx1 = fmaxf(mx1, __shfl_xor_sync(0xffffffffu, mx1, 2));
        float mn0 = fmaxf(m0, mx0), mn1 = fmaxf(m1, mx1);
        float fac0 = ex2(m0 - mn0), fac1 = ex2(m1 - mn1);

        float s0 = 0.f, s1 = 0.f;
#pragma unroll
        for (int nt = 0; nt < 8; nt++) {
            float p0 = ex2(sc[nt][0] - mn0);
            float p1 = ex2(sc[nt][1] - mn0);
            float p2 = ex2(sc[nt][2] - mn1);
            float p3 = ex2(sc[nt][3] - mn1);
            s0 += p0 + p1;
            s1 += p2 + p3;
            sc[nt][0] = f2tff(p0);
            sc[nt][1] = f2tff(p1);
            sc[nt][2] = f2tff(p2);
            sc[nt][3] = f2tff(p3);
        }
        s0 += __shfl_xor_sync(0xffffffffu, s0, 1);
        s0 += __shfl_xor_sync(0xffffffffu, s0, 2);
        s1 += __shfl_xor_sync(0xffffffffu, s1, 1);
        s1 += __shfl_xor_sync(0xffffffffu, s1, 2);
        l0 = l0 * fac0 + s0;
        l1 = l1 * fac1 + s1;
        m0 = mn0;
        m1 = mn1;
#pragma unroll
        for (int dn = 0; dn < 8; dn++) {
            o[dn][0] *= fac0; o[dn][1] *= fac0;
            o[dn][2] *= fac1; o[dn][3] *= fac1;
        }

#pragma unroll
        for (int k8 = 0; k8 < 8; k8++) {
            uint32_t af[4] = {__float_as_uint(sc[k8][0]), __float_as_uint(sc[k8][2]),
                              __float_as_uint(sc[k8][1]), __float_as_uint(sc[k8][3])};
#pragma unroll
            for (int dn = 0; dn < 8; dn++)
                mma8(o[dn], af,
                     Vs[cur][k8 * 8 + lq][dn * 8 + lr],
                     Vs[cur][k8 * 8 + lq + 4][dn * 8 + lr]);
        }
        __syncthreads();
    }

    // ---- epilogue: normalize + tf32-round, write PACKED aop[kc][row][20] ----
    float i0 = 1.0f / l0, i1 = 1.0f / l1;
    int grow = b * Ss + q0 + warp * 16 + lr;
#pragma unroll
    for (int dn = 0; dn < 8; dn++) {
        int e = dn * 8 + (lq << 1);           // 0..62, even
        int kc = h * 4 + (e >> 4);
        int ki = e & 15;
        float* p0 = AOP + ((size_t)kc * 4096 + grow) * 20 + ki;
        float* p1 = AOP + ((size_t)kc * 4096 + grow + 8) * 20 + ki;
        *(float2*)p0 = make_float2(f2tff(o[dn][0] * i0), f2tff(o[dn][1] * i0));
        *(float2*)p1 = make_float2(f2tff(o[dn][2] * i1), f2tff(o[dn][3] * i1));
    }
}

// ---------------------------------------------------------------------------
extern "C" void kernel_launch(void* const* d_in, const int* in_sizes, int n_in,
                              void* d_out, int out_size) {
    const float* x = (const float*)d_in[0];
    const float* w_qkv = (const float*)d_in[1];
    const float* w_out = (const float*)d_in[2];
    const float* freqs = (const float*)d_in[3];
    float* out = (float*)d_out;

    float *qkv, *q, *k, *v, *xp, *wp, *wop, *aop;
    cudaGetSymbolAddress((void**)&qkv, g_qkv);
    cudaGetSymbolAddress((void**)&q, g_q);
    cudaGetSymbolAddress((void**)&k, g_k);
    cudaGetSymbolAddress((void**)&v, g_v);
    cudaGetSymbolAddress((void**)&xp, g_xp);
    cudaGetSymbolAddress((void**)&wp, g_wp);
    cudaGetSymbolAddress((void**)&wop, g_wop);
    cudaGetSymbolAddress((void**)&aop, g_aop);

    cudaFuncSetAttribute(attn_kernel,
                         cudaFuncAttributeMaxDynamicSharedMemorySize,
                         ATTN_SMEM_BYTES);
    cudaFuncSetAttribute(gemm_packed,
                         cudaFuncAttributeMaxDynamicSharedMemorySize,
                         GEMM_SMEM);

    // 0) Pack operands (tf32, padded conflict-free layouts, contiguous tiles)
    pack_a<<<(4096 * 1024) / 256, 256>>>(x, xp);
    pack_b<<<(1024 * 3072) / 256, 256>>>(w_qkv, wp, 3072);
    pack_b<<<(1024 * 1024) / 256, 256>>>(w_out, wop, 1024);

    // 1) QKV projection: [4096,1024] @ [1024,3072], 256x128 tiles
    gemm_packed<<<dim3(24, 16), 256, GEMM_SMEM>>>(xp, wp, qkv, 3072);
    // 2) RoPE + head transpose + tf32 round
    rope_kernel<<<(Bb * Ss * 32) / 256, 256>>>(qkv, freqs, q, k, v);
    // 3) Causal flash attention (writes packed aop)
    attn_kernel<<<dim3(Ss / 128, Hh, Bb), 256, ATTN_SMEM_BYTES>>>(q, k, v, aop);
    // 4) Output projection: [4096,1024] @ [1024,1024], 256x128 tiles
    gemm_packed<<<dim3(8, 16), 256, GEMM_SMEM>>>(aop, wop, out, 1024);
}

// round 10
// speedup vs baseline: 1.1736x; 1.1026x over previous
#include <cuda_runtime.h>
#include <cstdint>

// Problem constants
static constexpr int Bb = 2, Ss = 2048, Hh = 16, DH = 64, Dd = 1024;
static constexpr int KC32 = 32;                 // 1024 / 32 k-steps

// Scratch (static device globals — no allocations allowed)
__device__ float g_q[Bb * Hh * Ss * DH];        // rope'd, scaled(*log2e), tf32
__device__ float g_k[Bb * Hh * Ss * DH];
__device__ float g_v[Bb * Hh * Ss * DH];
__device__ float g_xp[32 * 4096 * 36];          // packed A gemm1 (tf32, pad 36)
__device__ float g_wp[32 * 24 * 4352];          // packed B w_qkv
__device__ float g_wop[32 * 8 * 4352];          // packed B w_out
__device__ float g_aop[32 * 4096 * 36];         // packed A gemm2 (attn out)
__device__ float g_cos[Ss * DH];                // cos(freqs)
__device__ float g_sin[Ss * DH];                // sin(freqs)

__device__ __forceinline__ uint32_t f2tf(float f) {
    uint32_t u;
    asm("cvt.rna.tf32.f32 %0, %1;" : "=r"(u) : "f"(f));
    return u;
}
__device__ __forceinline__ float f2tff(float f) { return __uint_as_float(f2tf(f)); }

__device__ __forceinline__ float ex2(float x) {
    float y;
    asm("ex2.approx.f32 %0, %1;" : "=f"(y) : "f"(x));
    return y;
}

__device__ __forceinline__ void cp16(void* smem_ptr, const void* gptr) {
    uint32_t sa = (uint32_t)__cvta_generic_to_shared(smem_ptr);
    asm volatile("cp.async.ca.shared.global [%0], [%1], 16;"
                 :: "r"(sa), "l"(gptr));
}

__device__ __forceinline__ void mma8(float (&c)[4], const uint32_t (&a)[4],
                                     uint32_t b0, uint32_t b1) {
    asm volatile(
        "mma.sync.aligned.m16n8k8.row.col.f32.tf32.tf32.f32 "
        "{%0,%1,%2,%3}, {%4,%5,%6,%7}, {%8,%9}, {%0,%1,%2,%3};"
        : "+f"(c[0]), "+f"(c[1]), "+f"(c[2]), "+f"(c[3])
        : "r"(a[0]), "r"(a[1]), "r"(a[2]), "r"(a[3]), "r"(b0), "r"(b1));
}

// ---- mbarrier + 1D bulk-copy helpers ----
__device__ __forceinline__ uint32_t s2u(const void* p) {
    return (uint32_t)__cvta_generic_to_shared(p);
}
__device__ __forceinline__ void mbar_init(uint32_t addr, uint32_t cnt) {
    asm volatile("mbarrier.init.shared.b64 [%0], %1;" :: "r"(addr), "r"(cnt));
}
__device__ __forceinline__ void mbar_expect_tx(uint32_t addr, uint32_t bytes) {
    asm volatile("mbarrier.arrive.expect_tx.shared.b64 _, [%0], %1;"
                 :: "r"(addr), "r"(bytes));
}
__device__ __forceinline__ void mbar_wait(uint32_t addr, uint32_t parity) {
    asm volatile(
        "{\n\t.reg .pred P;\n"
        "W%=:\n\t"
        "mbarrier.try_wait.parity.shared.b64 P, [%0], %1;\n\t"
        "@!P bra W%=;\n\t}"
        :: "r"(addr), "r"(parity) : "memory");
}
__device__ __forceinline__ void bulk_g2s(uint32_t dst, const void* src,
                                         uint32_t bytes, uint32_t mbar) {
    asm volatile(
        "cp.async.bulk.shared::cta.global.mbarrier::complete_tx::bytes "
        "[%0], [%1], %2, [%3];"
        :: "r"(dst), "l"(src), "r"(bytes), "r"(mbar) : "memory");
}

// ---------------------------------------------------------------------------
// Pack kernels: contiguous, padded, tf32-rounded tiles (BK=32 layouts).
// A: X[M][1024] -> Xp[kc][M][36]  (cols 0-31 data, 32-35 pad)
// ---------------------------------------------------------------------------
__global__ __launch_bounds__(256) void pack_a(
    const float* __restrict__ X, float* __restrict__ Xp) {
    int idx = blockIdx.x * 256 + threadIdx.x;   // over 4096*1024
    int m = idx >> 10, k = idx & 1023;
    Xp[((size_t)(k >> 5) * 4096 + m) * 36 + (k & 31)] = f2tff(X[idx]);
}

// B: W[1024][N] -> Wp[kc][nb][kr(32)][136]  (cols 0-127 data, pad 8)
__global__ __launch_bounds__(256) void pack_b(
    const float* __restrict__ W, float* __restrict__ Wp, int N) {
    int idx = blockIdx.x * 256 + threadIdx.x;   // over 1024*N
    int k = idx / N, n = idx - k * N;
    size_t chunk = (size_t)(k >> 5) * (N >> 7) + (n >> 7);
    Wp[chunk * 4352 + (k & 31) * 136 + (n & 127)] = f2tff(W[idx]);
}

// cos/sin tables for the fused-rope GEMM epilogue (precise sincosf, once).
__global__ __launch_bounds__(256) void trig_kernel(
    const float* __restrict__ freqs, float* __restrict__ cb,
    float* __restrict__ sb) {
    int i = blockIdx.x * 256 + threadIdx.x;     // 2048*64
    float s, c;
    sincosf(freqs[i], &s, &c);
    cb[i] = c;
    sb[i] = s;
}

// ---------------------------------------------------------------------------
// Shared GEMM mainloop config: 256x128 tile, BK=32, 8 warps (4x2 of 64x64),
// 3-stage mbarrier + bulk-copy pipeline.
// ---------------------------------------------------------------------------
static constexpr int AST_W = 256 * 36;          // 9216 words
static constexpr int BST_W = 32 * 136;          // 4352 words
static constexpr int STG_W = AST_W + BST_W;     // 13568 words = 54272 B
static constexpr int GEMM_SMEM = 3 * STG_W * 4; // 162816 B

// The mainloop body, shared by both GEMM variants via macro-free duplication.
#define GEMM_MAINLOOP(ApPtr, BpPtr, NBv)                                      \
    extern __shared__ uint32_t gsm[];                                         \
    __shared__ uint64_t gmb[3];                                               \
    const int tid = threadIdx.x, lane = tid & 31, warp = tid >> 5;            \
    const int wm = (warp >> 1) * 64, wn = (warp & 1) * 64;                    \
    const int lr = lane >> 2, lq = lane & 3;                                  \
    const int bm = blockIdx.y * 256, nb = blockIdx.x;                         \
    const uint32_t mb0 = s2u(gmb);                                            \
    const uint32_t smem_base = s2u(gsm);                                      \
    if (tid == 0) {                                                           \
        mbar_init(mb0, 1);                                                    \
        mbar_init(mb0 + 8, 1);                                                \
        mbar_init(mb0 + 16, 1);                                               \
        asm volatile("fence.proxy.async.shared::cta;" ::: "memory");          \
    }                                                                         \
    __syncthreads();                                                          \
    auto issue = [&](int i) {                                                 \
        if (tid == 0) {                                                       \
            int st = i % 3;                                                   \
            uint32_t m = mb0 + st * 8;                                        \
            uint32_t dst = smem_base + st * (STG_W * 4);                      \
            mbar_expect_tx(m, STG_W * 4);                                     \
            bulk_g2s(dst, (ApPtr) + ((size_t)i * 4096 + bm) * 36,             \
                     AST_W * 4, m);                                           \
            bulk_g2s(dst + AST_W * 4, (BpPtr) + (size_t)(i * (NBv) + nb) *    \
                     BST_W, BST_W * 4, m);                                    \
        }                                                                     \
    };                                                                        \
    float acc[4][8][4];                                                       \
    _Pragma("unroll") for (int mt = 0; mt < 4; mt++)                          \
        _Pragma("unroll") for (int nt = 0; nt < 8; nt++)                      \
            _Pragma("unroll") for (int i = 0; i < 4; i++)                     \
                acc[mt][nt][i] = 0.f;                                         \
    issue(0);                                                                 \
    issue(1);                                                                 \
    issue(2);                                                                 \
    for (int i = 0; i < KC32; i++) {                                          \
        const int st = i % 3;                                                 \
        mbar_wait(mb0 + st * 8, (i / 3) & 1);                                 \
        const uint32_t* As = gsm + st * STG_W;                                \
        const uint32_t* Bs = As + AST_W;                                      \
        _Pragma("unroll") for (int ks = 0; ks < 32; ks += 8) {                \
            uint32_t a[4][4], b[8][2];                                        \
            _Pragma("unroll") for (int mt = 0; mt < 4; mt++) {                \
                int r0 = (wm + mt * 16 + lr) * 36, c0 = ks + lq;              \
                a[mt][0] = As[r0 + c0];                                       \
                a[mt][1] = As[r0 + 288 + c0];                                 \
                a[mt][2] = As[r0 + c0 + 4];                                   \
                a[mt][3] = As[r0 + 288 + c0 + 4];                             \
            }                                                                 \
            _Pragma("unroll") for (int nt = 0; nt < 8; nt++) {                \
                int cc = wn + nt * 8 + lr, kr = ks + lq;                      \
                b[nt][0] = Bs[kr * 136 + cc];                                 \
                b[nt][1] = Bs[(kr + 4) * 136 + cc];                           \
            }                                                                 \
            _Pragma("unroll") for (int mt = 0; mt < 4; mt++)                  \
                _Pragma("unroll") for (int nt = 0; nt < 8; nt++)              \
                    mma8(acc[mt][nt], a[mt], b[nt][0], b[nt][1]);             \
        }                                                                     \
        __syncthreads();                                                      \
        if (i + 3 < KC32) issue(i + 3);                                       \
    }

// ---------------------------------------------------------------------------
// GEMM 1: QKV projection with FUSED RoPE epilogue.
// Each warp's 64-col slice = exactly one (type, head). RoPE partners are the
// warp's nt and nt+4 accumulator tiles (d vs d+32) — rotated in-register.
// Writes q (scaled by 0.125*log2e), k, v directly in [b,h,s,d] layout, tf32.
// ---------------------------------------------------------------------------
__global__ __launch_bounds__(256) void gemm_qkv(
    const float* __restrict__ Ap, const float* __restrict__ Bp,
    float* __restrict__ Qo, float* __restrict__ Ko, float* __restrict__ Vo,
    const float* __restrict__ cb, const float* __restrict__ sb) {
    GEMM_MAINLOOP(Ap, Bp, 24)

    const int col0 = nb * 128 + wn;             // 64-col slice start
    const int type = col0 >> 10;                // 0=q, 1=k, 2=v
    const int h = (col0 >> 6) & 15;
    const float qsc = 0.125f * 1.4426950408889634f;

    if (type < 2) {
        float* dst0 = (type == 0) ? Qo : Ko;
#pragma unroll
        for (int mt = 0; mt < 4; mt++) {
#pragma unroll
            for (int e2 = 0; e2 < 2; e2++) {
                int r = bm + wm + mt * 16 + lr + 8 * e2;
                int s = r & 2047, bb = r >> 11;
                float* dst = dst0 + ((size_t)(bb * Hh + h) * Ss + s) * 64;
                const float* cr = cb + s * 64;
                const float* sr = sb + s * 64;
#pragma unroll
                for (int nt = 0; nt < 4; nt++) {
                    int dlo = nt * 8 + (lq << 1);
                    float2 clo = *(const float2*)&cr[dlo];
                    float2 slo = *(const float2*)&sr[dlo];
                    float2 chi = *(const float2*)&cr[dlo + 32];
                    float2 shi = *(const float2*)&sr[dlo + 32];
                    float al0 = acc[mt][nt][2 * e2], al1 = acc[mt][nt][2 * e2 + 1];
                    float ah0 = acc[mt][nt + 4][2 * e2], ah1 = acc[mt][nt + 4][2 * e2 + 1];
                    float ol0 = al0 * clo.x - ah0 * slo.x;
                    float ol1 = al1 * clo.y - ah1 * slo.y;
                    float oh0 = ah0 * chi.x + al0 * shi.x;
                    float oh1 = ah1 * chi.y + al1 * shi.y;
                    if (type == 0) { ol0 *= qsc; ol1 *= qsc; oh0 *= qsc; oh1 *= qsc; }
                    *(float2*)&dst[dlo] = make_float2(f2tff(ol0), f2tff(ol1));
                    *(float2*)&dst[dlo + 32] = make_float2(f2tff(oh0), f2tff(oh1));
                }
            }
        }
    } else {
#pragma unroll
        for (int mt = 0; mt < 4; mt++) {
#pragma unroll
            for (int e2 = 0; e2 < 2; e2++) {
                int r = bm + wm + mt * 16 + lr + 8 * e2;
                int s = r & 2047, bb = r >> 11;
                float* dst = Vo + ((size_t)(bb * Hh + h) * Ss + s) * 64;
#pragma unroll
                for (int nt = 0; nt < 8; nt++) {
                    int d = nt * 8 + (lq << 1);
                    *(float2*)&dst[d] =
                        make_float2(f2tff(acc[mt][nt][2 * e2]),
                                    f2tff(acc[mt][nt][2 * e2 + 1]));
                }
            }
        }
    }
}

// ---------------------------------------------------------------------------
// GEMM 2: output projection, plain row-major epilogue.
// ---------------------------------------------------------------------------
__global__ __launch_bounds__(256) void gemm_out(
    const float* __restrict__ Ap, const float* __restrict__ Bp,
    float* __restrict__ C) {
    GEMM_MAINLOOP(Ap, Bp, 8)

#pragma unroll
    for (int mt = 0; mt < 4; mt++)
#pragma unroll
        for (int nt = 0; nt < 8; nt++) {
            int row = bm + wm + mt * 16 + lr;
            int col = (nb << 7) + wn + nt * 8 + (lq << 1);
            *(float2*)&C[(size_t)row * 1024 + col] =
                make_float2(acc[mt][nt][0], acc[mt][nt][1]);
            *(float2*)&C[(size_t)(row + 8) * 1024 + col] =
                make_float2(acc[mt][nt][2], acc[mt][nt][3]);
        }
}

// ---------------------------------------------------------------------------
// Causal flash attention (R6/R9 proven core). Br=128, Bc=64.
// Epilogue writes PACKED A for gemm2: aop[kc][row][36], kc = (h*64+d)>>5.
// ---------------------------------------------------------------------------
static constexpr int KS_WORDS = 64 * 68;
static constexpr int VS_WORDS = 64 * 72;
static constexpr int ATTN_SMEM_BYTES = (2 * KS_WORDS + 2 * VS_WORDS) * 4;  // 71680

__global__ __launch_bounds__(256) void attn_kernel(
    const float* __restrict__ Q, const float* __restrict__ K,
    const float* __restrict__ V, float* __restrict__ AOP) {
    extern __shared__ uint32_t dynsmem[];
    uint32_t (*Ks)[64][68] = reinterpret_cast<uint32_t (*)[64][68]>(dynsmem);
    uint32_t (*Vs)[64][72] =
        reinterpret_cast<uint32_t (*)[64][72]>(dynsmem + 2 * KS_WORDS);

    const int qt = gridDim.x - 1 - blockIdx.x;
    const int h = blockIdx.y, b = blockIdx.z;
    const int tid = threadIdx.x, lane = tid & 31, warp = tid >> 5;
    const int lr = lane >> 2, lq = lane & 3;
    const int q0 = qt * 128;

    const size_t bh = (size_t)(b * Hh + h) * Ss;
    const float* Qg = Q + (bh + q0) * 64;
    const float* Kg = K + bh * 64;
    const float* Vg = V + bh * 64;

    uint32_t qf[8][4];
    {
        int r0 = warp * 16 + lr;
#pragma unroll
        for (int k8 = 0; k8 < 8; k8++) {
            int c = k8 * 8 + lq;
            qf[k8][0] = __float_as_uint(Qg[r0 * 64 + c]);
            qf[k8][1] = __float_as_uint(Qg[(r0 + 8) * 64 + c]);
            qf[k8][2] = __float_as_uint(Qg[r0 * 64 + c + 4]);
            qf[k8][3] = __float_as_uint(Qg[(r0 + 8) * 64 + c + 4]);
        }
    }

    float o[8][4];
#pragma unroll
    for (int dn = 0; dn < 8; dn++)
#pragma unroll
        for (int i = 0; i < 4; i++) o[dn][i] = 0.f;
    float m0 = -1e30f, m1 = -1e30f, l0 = 0.f, l1 = 0.f;

    const int lrow = tid >> 4;
    const int lcol = (tid & 15) << 2;

    auto issue_tile = [&](int jt, int buf) {
        const float* kb = Kg + (size_t)(jt * 64) * 64;
        const float* vb = Vg + (size_t)(jt * 64) * 64;
#pragma unroll
        for (int u = 0; u < 4; u++) {
            int r = lrow + 16 * u;
            cp16(&Ks[buf][r][lcol], kb + r * 64 + lcol);
            int g = r & 7;
            int slot = (r & ~7) | ((g & 1) ? ((g >> 1) + 4) : (g >> 1));
            cp16(&Vs[buf][slot][lcol], vb + r * 64 + lcol);
        }
        asm volatile("cp.async.commit_group;");
    };

    const int jmax = 2 * qt + 1;
    issue_tile(0, 0);

    for (int jt = 0; jt <= jmax; jt++) {
        const int cur = jt & 1;
        if (jt < jmax) {
            issue_tile(jt + 1, cur ^ 1);
            asm volatile("cp.async.wait_group 1;");
        } else {
            asm volatile("cp.async.wait_group 0;");
        }
        __syncthreads();

        float sc[8][4];
#pragma unroll
        for (int nt = 0; nt < 8; nt++)
#pragma unroll
            for (int i = 0; i < 4; i++) sc[nt][i] = 0.f;
#pragma unroll
        for (int k8 = 0; k8 < 8; k8++)
#pragma unroll
            for (int nt = 0; nt < 8; nt++)
                mma8(sc[nt], qf[k8],
                     Ks[cur][nt * 8 + lr][k8 * 8 + lq],
                     Ks[cur][nt * 8 + lr][k8 * 8 + lq + 4]);

        if (jt >= 2 * qt) {
            int r1 = q0 + warp * 16 + lr;
#pragma unroll
            for (int nt = 0; nt < 8; nt++) {
                int key = jt * 64 + nt * 8 + (lq << 1);
                if (key > r1) sc[nt][0] = -1e30f;
                if (key + 1 > r1) sc[nt][1] = -1e30f;
                if (key > r1 + 8) sc[nt][2] = -1e30f;
                if (key + 1 > r1 + 8) sc[nt][3] = -1e30f;
            }
        }

        float mx0 = -1e30f, mx1 = -1e30f;
#pragma unroll
        for (int nt = 0; nt < 8; nt++) {
            mx0 = fmaxf(mx0, fmaxf(sc[nt][0], sc[nt][1]));
            mx1 = fmaxf(mx1, fmaxf(sc[nt][2], sc[nt][3]));
        }
        mx0 = fmaxf(mx0, __shfl_xor_sync(0xffffffffu, mx0, 1));
        mx0 = fmaxf(mx0, __shfl_xor_sync(0xffffffffu, mx0, 2));
        mx1 = fmaxf(mx1, __shfl_xor_sync(0xffffffffu, mx1, 1));
        mx1 = fmaxf(mx1, __shfl_xor_sync(0xffffffffu, mx1, 2));
        float mn0 = fmaxf(m0, mx0), mn1 = fmaxf(m1, mx1);
        float fac0 = ex2(m0 - mn0), fac1 = ex2(m1 - mn1);

        float s0 = 0.f, s1 = 0.f;
#pragma unroll
        for (int nt = 0; nt < 8; nt++) {
            float p0 = ex2(sc[nt][0] - mn0);
            float p1 = ex2(sc[nt][1] - mn0);
            float p2 = ex2(sc[nt][2] - mn1);
            float p3 = ex2(sc[nt][3] - mn1);
            s0 += p0 + p1;
            s1 += p2 + p3;
            sc[nt][0] = f2tff(p0);
            sc[nt][1] = f2tff(p1);
            sc[nt][2] = f2tff(p2);
            sc[nt][3] = f2tff(p3);
        }
        s0 += __shfl_xor_sync(0xffffffffu, s0, 1);
        s0 += __shfl_xor_sync(0xffffffffu, s0, 2);
        s1 += __shfl_xor_sync(0xffffffffu, s1, 1);
        s1 += __shfl_xor_sync(0xffffffffu, s1, 2);
        l0 = l0 * fac0 + s0;
        l1 = l1 * fac1 + s1;
        m0 = mn0;
        m1 = mn1;
#pragma unroll
        for (int dn = 0; dn < 8; dn++) {
            o[dn][0] *= fac0; o[dn][1] *= fac0;
            o[dn][2] *= fac1; o[dn][3] *= fac1;
        }

#pragma unroll
        for (int k8 = 0; k8 < 8; k8++) {
            uint32_t af[4] = {__float_as_uint(sc[k8][0]), __float_as_uint(sc[k8][2]),
                              __float_as_uint(sc[k8][1]), __float_as_uint(sc[k8][3])};
#pragma unroll
            for (int dn = 0; dn < 8; dn++)
                mma8(o[dn], af,
                     Vs[cur][k8 * 8 + lq][dn * 8 + lr],
                     Vs[cur][k8 * 8 + lq + 4][dn * 8 + lr]);
        }
        __syncthreads();
    }

    // ---- epilogue: normalize + tf32, write PACKED aop[kc][row][36] ----
    float i0 = 1.0f / l0, i1 = 1.0f / l1;
    int grow = b * Ss + q0 + warp * 16 + lr;
#pragma unroll
    for (int dn = 0; dn < 8; dn++) {
        int e = dn * 8 + (lq << 1);           // d value, 0..62 even
        int kc = h * 2 + (e >> 5);            // global k = h*64+e, BK=32
        int ki = e & 31;
        float* p0 = AOP + ((size_t)kc * 4096 + grow) * 36 + ki;
        float* p1 = AOP + ((size_t)kc * 4096 + grow + 8) * 36 + ki;
        *(float2*)p0 = make_float2(f2tff(o[dn][0] * i0), f2tff(o[dn][1] * i0));
        *(float2*)p1 = make_float2(f2tff(o[dn][2] * i1), f2tff(o[dn][3] * i1));
    }
}

// ---------------------------------------------------------------------------
extern "C" void kernel_launch(void* const* d_in, const int* in_sizes, int n_in,
                              void* d_out, int out_size) {
    const float* x = (const float*)d_in[0];
    const float* w_qkv = (const float*)d_in[1];
    const float* w_out = (const float*)d_in[2];
    const float* freqs = (const float*)d_in[3];
    float* out = (float*)d_out;

    float *q, *k, *v, *xp, *wp, *wop, *aop, *cb, *sb;
    cudaGetSymbolAddress((void**)&q, g_q);
    cudaGetSymbolAddress((void**)&k, g_k);
    cudaGetSymbolAddress((void**)&v, g_v);
    cudaGetSymbolAddress((void**)&xp, g_xp);
    cudaGetSymbolAddress((void**)&wp, g_wp);
    cudaGetSymbolAddress((void**)&wop, g_wop);
    cudaGetSymbolAddress((void**)&aop, g_aop);
    cudaGetSymbolAddress((void**)&cb, g_cos);
    cudaGetSymbolAddress((void**)&sb, g_sin);

    cudaFuncSetAttribute(attn_kernel,
                         cudaFuncAttributeMaxDynamicSharedMemorySize,
                         ATTN_SMEM_BYTES);
    cudaFuncSetAttribute(gemm_qkv,
                         cudaFuncAttributeMaxDynamicSharedMemorySize,
                         GEMM_SMEM);
    cudaFuncSetAttribute(gemm_out,
                         cudaFuncAttributeMaxDynamicSharedMemorySize,
                         GEMM_SMEM);

    // 0) Pack operands + trig tables
    pack_a<<<(4096 * 1024) / 256, 256>>>(x, xp);
    pack_b<<<(1024 * 3072) / 256, 256>>>(w_qkv, wp, 3072);
    pack_b<<<(1024 * 1024) / 256, 256>>>(w_out, wop, 1024);
    trig_kernel<<<(Ss * DH) / 256, 256>>>(freqs, cb, sb);

    // 1) QKV projection + fused RoPE -> q/k/v in [b,h,s,d] (tf32)
    gemm_qkv<<<dim3(24, 16), 256, GEMM_SMEM>>>(xp, wp, q, k, v, cb, sb);
    // 2) Causal flash attention (writes packed aop)
    attn_kernel<<<dim3(Ss / 128, Hh, Bb), 256, ATTN_SMEM_BYTES>>>(q, k, v, aop);
    // 3) Output projection
    gemm_out<<<dim3(8, 16), 256, GEMM_SMEM>>>(aop, wop, out);
}